// round 1
// baseline (speedup 1.0000x reference)
#include <cuda_runtime.h>
#include <math.h>

#define NN  4096
#define EMB 256
#define NH  4
#define HC  64
#define TI  128
#define TJ  64

typedef unsigned long long ull;

// ---- device scratch (no allocations allowed) ----
__device__ float g_h[NN*EMB];     // h = x @ W_lin
__device__ float g_att[NN*EMB];   // attention output (+bias_att)
__device__ float g_y[NN*EMB];     // pre-LN linear output
__device__ float g_r[NH*NN];      // e^{0.8 s_i}
__device__ float g_a[NH*NN];      // e^{t_j}
__device__ float g_b[NH*NN];      // e^{0.2 t_j}

__device__ __forceinline__ void fma2(ull& d, ull a, ull b) {
    asm("fma.rn.f32x2 %0, %1, %2, %0;" : "+l"(d) : "l"(a), "l"(b));
}
__device__ __forceinline__ ull dup2(float x) {
    ull r; asm("mov.b64 %0, {%1, %1};" : "=l"(r) : "f"(x)); return r;
}

// ---------------------------------------------------------------------------
// Generic fp32 GEMM: Co[M,Nc] = A[M,K] @ B[K,Nc] (+ bias). 64x64 tile, 256 thr.
// ---------------------------------------------------------------------------
__global__ __launch_bounds__(256) void gemm_bias_kernel(
    const float* __restrict__ A, const float* __restrict__ B,
    const float* __restrict__ bias, float* __restrict__ Co,
    int M, int Nc, int K)
{
    __shared__ float as[16][68];   // [k][m] transposed
    __shared__ float bs[16][68];   // [k][n]
    const int m0 = blockIdx.y * 64, n0 = blockIdx.x * 64;
    const int tid = threadIdx.x;
    const int ty = tid >> 4, tx = tid & 15;

    float acc[4][4];
#pragma unroll
    for (int i = 0; i < 4; i++)
#pragma unroll
        for (int j = 0; j < 4; j++) acc[i][j] = 0.f;

    for (int k0 = 0; k0 < K; k0 += 16) {
        {   // A tile 64 rows x 16 cols
            int r = tid >> 2, c4 = tid & 3;
            float4 v = *(const float4*)&A[(m0 + r) * K + k0 + c4 * 4];
            as[c4*4+0][r] = v.x; as[c4*4+1][r] = v.y;
            as[c4*4+2][r] = v.z; as[c4*4+3][r] = v.w;
        }
        {   // B tile 16 rows x 64 cols
            int r = tid >> 4, c4 = tid & 15;
            *(float4*)&bs[r][c4*4] = *(const float4*)&B[(k0 + r) * Nc + n0 + c4 * 4];
        }
        __syncthreads();
#pragma unroll
        for (int k = 0; k < 16; k++) {
            float4 av = *(const float4*)&as[k][ty * 4];
            float4 bv = *(const float4*)&bs[k][tx * 4];
            float a4[4] = {av.x, av.y, av.z, av.w};
            float b4[4] = {bv.x, bv.y, bv.z, bv.w};
#pragma unroll
            for (int i = 0; i < 4; i++)
#pragma unroll
                for (int j = 0; j < 4; j++) acc[i][j] += a4[i] * b4[j];
        }
        __syncthreads();
    }
#pragma unroll
    for (int i = 0; i < 4; i++) {
        int row = m0 + ty * 4 + i;
#pragma unroll
        for (int j = 0; j < 4; j++) {
            int col = n0 + tx * 4 + j;
            float v = acc[i][j];
            if (bias) v += bias[col];
            Co[row * Nc + col] = v;
        }
    }
}

// ---------------------------------------------------------------------------
// Prep: per (head, node) compute s = h . att_dst, t = h . att_src, then
// r = e^{0.8 s}, a = e^t, b = e^{0.2 t}. One warp per (head,node).
// ---------------------------------------------------------------------------
__global__ __launch_bounds__(256) void prep_kernel(
    const float* __restrict__ att_src, const float* __restrict__ att_dst)
{
    int wid  = blockIdx.x * 8 + (threadIdx.x >> 5);   // 0 .. NH*NN-1
    int lane = threadIdx.x & 31;
    int hd = wid >> 12;         // / NN
    int n  = wid & (NN - 1);
    const float* hp = g_h + n * EMB + hd * HC;
    float h0 = hp[lane], h1 = hp[lane + 32];
    float s = h0 * att_dst[hd*HC + lane] + h1 * att_dst[hd*HC + lane + 32];
    float t = h0 * att_src[hd*HC + lane] + h1 * att_src[hd*HC + lane + 32];
#pragma unroll
    for (int o = 16; o; o >>= 1) {
        s += __shfl_xor_sync(0xffffffffu, s, o);
        t += __shfl_xor_sync(0xffffffffu, t, o);
    }
    if (lane == 0) {
        g_r[wid] = expf(0.8f * s);
        g_a[wid] = expf(t);
        g_b[wid] = expf(0.2f * t);
    }
}

// ---------------------------------------------------------------------------
// Fused GAT aggregation. Block = (128 dest rows) x (1 head). For each 64-wide
// source tile: compute c_ij = mask * max(r_i*a_j, b_j) into smem + accumulate
// per-row denominators, then register-tiled GEMM vs the h tile (f32x2 FMA).
// Writes normalized output + bias_att.
// ---------------------------------------------------------------------------
__global__ __launch_bounds__(128) void gat_kernel(
    const int* __restrict__ adj, const float* __restrict__ bias_att)
{
    extern __shared__ float sm[];
    float* c_sm = sm;                       // [TJ][TI+4]
    float* h_sm = c_sm + TJ * (TI + 4);     // [TJ][HC]
    float* r_sm = h_sm + TJ * HC;           // [TI]
    float* d_sm = r_sm + TI;                // [TI] denominators

    const int hd = blockIdx.y;
    const int i0 = blockIdx.x * TI;
    const int tid = threadIdx.x;
    const int lane = tid & 31;
    const int w = tid >> 5;                 // warp id (0..3)

    if (tid < TI) { r_sm[tid] = g_r[hd * NN + i0 + tid]; d_sm[tid] = 0.f; }

    const int ty = tid >> 3;   // 0..15 -> i block of 8
    const int tx = tid & 7;    // 0..7  -> c block of 8

    ull acc[8][4];
#pragma unroll
    for (int i = 0; i < 8; i++)
#pragma unroll
        for (int j = 0; j < 4; j++) acc[i][j] = 0ull;

    const float* ga = g_a + hd * NN;
    const float* gb = g_b + hd * NN;

    for (int j0 = 0; j0 < NN; j0 += TJ) {
        __syncthreads();   // protect c_sm/h_sm reuse vs previous GEMM reads

        // load h tile: 64 rows x 64 floats (this head's slice)
#pragma unroll
        for (int rr = 0; rr < 8; rr++) {
            int e = rr * 128 + tid;          // 0..1023 float4 slots
            int j = e >> 4, c4 = e & 15;
            *(float4*)&h_sm[j * HC + c4 * 4] =
                *(const float4*)&g_h[(j0 + j) * EMB + hd * HC + c4 * 4];
        }

        // phase C: warp w owns dest rows [w*32, w*32+32)
#pragma unroll 4
        for (int ii = 0; ii < 32; ii++) {
            int i  = w * 32 + ii;
            int gi = i0 + i;
            float ri = r_sm[i];
            float part = 0.f;
            const int* arow = adj + gi * NN + j0;
#pragma unroll
            for (int jt = 0; jt < 2; jt++) {
                int j  = jt * 32 + lane;
                int gj = j0 + j;
                int m  = __ldg(arow + j);
                float cv = 0.f;
                if (m != 0 || gj == gi)          // adj with forced self-loop
                    cv = fmaxf(ri * __ldg(ga + gj), __ldg(gb + gj));
                c_sm[j * (TI + 4) + i] = cv;
                part += cv;
            }
#pragma unroll
            for (int o = 16; o; o >>= 1) part += __shfl_xor_sync(0xffffffffu, part, o);
            if (lane == 0) d_sm[i] += part;
        }
        __syncthreads();

        // GEMM: out[i][c] += sum_j c_sm[j][i] * h_sm[j][c]
        const float* cbase = c_sm + ty * 8;
        const float* hbase = h_sm + tx * 8;
#pragma unroll 8
        for (int j = 0; j < TJ; j++) {
            float4 cA = *(const float4*)(cbase + j * (TI + 4));
            float4 cB = *(const float4*)(cbase + j * (TI + 4) + 4);
            ulonglong2 hA = *(const ulonglong2*)(hbase + j * HC);
            ulonglong2 hB = *(const ulonglong2*)(hbase + j * HC + 4);
            ull cd[8] = { dup2(cA.x), dup2(cA.y), dup2(cA.z), dup2(cA.w),
                          dup2(cB.x), dup2(cB.y), dup2(cB.z), dup2(cB.w) };
#pragma unroll
            for (int ii = 0; ii < 8; ii++) {
                fma2(acc[ii][0], cd[ii], hA.x);
                fma2(acc[ii][1], cd[ii], hA.y);
                fma2(acc[ii][2], cd[ii], hB.x);
                fma2(acc[ii][3], cd[ii], hB.y);
            }
        }
    }
    __syncthreads();

    // epilogue: normalize + bias_att
#pragma unroll
    for (int ii = 0; ii < 8; ii++) {
        int i = ty * 8 + ii;
        float inv = 1.0f / d_sm[i];
        int row = i0 + i;
#pragma unroll
        for (int cc = 0; cc < 4; cc++) {
            ull v = acc[ii][cc];
            float lo = __uint_as_float((unsigned)(v & 0xffffffffull));
            float hi = __uint_as_float((unsigned)(v >> 32));
            int col = hd * HC + tx * 8 + cc * 2;
            g_att[row * EMB + col]     = lo * inv + __ldg(bias_att + col);
            g_att[row * EMB + col + 1] = hi * inv + __ldg(bias_att + col + 1);
        }
    }
}

// ---------------------------------------------------------------------------
// LayerNorm over last dim (256), one block per row.
// ---------------------------------------------------------------------------
__global__ __launch_bounds__(256) void ln_kernel(
    const float* __restrict__ gamma, const float* __restrict__ beta,
    float* __restrict__ out)
{
    __shared__ float red1[8], red2[8];
    int row = blockIdx.x;
    int tid = threadIdx.x;
    float v = g_y[row * EMB + tid];

    float s = v;
#pragma unroll
    for (int o = 16; o; o >>= 1) s += __shfl_xor_sync(0xffffffffu, s, o);
    if ((tid & 31) == 0) red1[tid >> 5] = s;
    __syncthreads();
    float mu = 0.f;
#pragma unroll
    for (int k = 0; k < 8; k++) mu += red1[k];
    mu *= (1.0f / EMB);

    float d = v - mu;
    float q = d * d;
#pragma unroll
    for (int o = 16; o; o >>= 1) q += __shfl_xor_sync(0xffffffffu, q, o);
    if ((tid & 31) == 0) red2[tid >> 5] = q;
    __syncthreads();
    float var = 0.f;
#pragma unroll
    for (int k = 0; k < 8; k++) var += red2[k];
    var *= (1.0f / EMB);

    out[row * EMB + tid] = d * rsqrtf(var + 1e-5f) * gamma[tid] + beta[tid];
}

// ---------------------------------------------------------------------------
extern "C" void kernel_launch(void* const* d_in, const int* in_sizes, int n_in,
                              void* d_out, int out_size)
{
    const float* x        = (const float*)d_in[0];
    const int*   adj      = (const int*)  d_in[1];
    const float* W_lin    = (const float*)d_in[2];
    const float* att_src  = (const float*)d_in[3];
    const float* att_dst  = (const float*)d_in[4];
    const float* bias_att = (const float*)d_in[5];
    const float* W_out    = (const float*)d_in[6];
    const float* b_out    = (const float*)d_in[7];
    const float* gamma    = (const float*)d_in[8];
    const float* beta     = (const float*)d_in[9];
    float* out = (float*)d_out;

    float *p_h, *p_att, *p_y;
    cudaGetSymbolAddress((void**)&p_h,   g_h);
    cudaGetSymbolAddress((void**)&p_att, g_att);
    cudaGetSymbolAddress((void**)&p_y,   g_y);

    const int gat_smem = (TJ * (TI + 4) + TJ * HC + TI + TI) * (int)sizeof(float); // 51200
    cudaFuncSetAttribute(gat_kernel, cudaFuncAttributeMaxDynamicSharedMemorySize, gat_smem);

    dim3 gemm_grid(EMB / 64, NN / 64);  // (4, 64)

    // 1) h = x @ W_lin
    gemm_bias_kernel<<<gemm_grid, 256>>>(x, W_lin, nullptr, p_h, NN, EMB, EMB);
    // 2) per-node attention scalars -> r, a, b
    prep_kernel<<<(NH * NN) / 8, 256>>>(att_src, att_dst);
    // 3) fused masked-softmax aggregation (+bias_att)
    dim3 gat_grid(NN / TI, NH);
    gat_kernel<<<gat_grid, 128, gat_smem>>>(adj, bias_att);
    // 4) y = att @ W_out + b_out
    gemm_bias_kernel<<<gemm_grid, 256>>>(p_att, W_out, b_out, p_y, NN, EMB, EMB);
    // 5) LayerNorm -> out
    ln_kernel<<<NN, 256>>>(gamma, beta, out);
}

// round 3
// speedup vs baseline: 2.4213x; 2.4213x over previous
#include <cuda_runtime.h>
#include <math.h>

#define NN  4096
#define EMB 256
#define NH  4
#define HC  64
#define TI  128
#define TJ  64
#define PADI 132   // c_sm row stride (floats), 16B-aligned

typedef unsigned long long ull;

// ---- device scratch (no allocations allowed) ----
__device__ float    g_h[NN*EMB];            // h = x @ W_lin
__device__ float    g_att[NN*EMB];          // attention output (+bias_att)
__device__ float    g_y[NN*EMB];            // pre-LN linear output
__device__ float    g_r[NH*NN];             // e^{0.8 s_i}
__device__ float    g_a[NH*NN];             // e^{t_j}
__device__ float    g_b[NH*NN];             // e^{0.2 t_j}
__device__ unsigned g_adjbits[NN*(NN/32)];  // adjacency bitmask, diag forced 1

__device__ __forceinline__ void fma2(ull& d, ull a, ull b) {
    asm("fma.rn.f32x2 %0, %1, %2, %0;" : "+l"(d) : "l"(a), "l"(b));
}
__device__ __forceinline__ ull dup2(float x) {
    ull r; asm("mov.b64 %0, {%1, %1};" : "=l"(r) : "f"(x)); return r;
}

// ---------------------------------------------------------------------------
// Generic fp32 GEMM: Co[M,Nc] = A[M,K] @ B[K,Nc] (+ bias). 64x64 tile, 256 thr.
// ---------------------------------------------------------------------------
__global__ __launch_bounds__(256) void gemm_bias_kernel(
    const float* __restrict__ A, const float* __restrict__ B,
    const float* __restrict__ bias, float* __restrict__ Co,
    int M, int Nc, int K)
{
    __shared__ float as[16][68];   // [k][m] transposed
    __shared__ float bs[16][68];   // [k][n]
    const int m0 = blockIdx.y * 64, n0 = blockIdx.x * 64;
    const int tid = threadIdx.x;
    const int ty = tid >> 4, tx = tid & 15;

    float acc[4][4];
#pragma unroll
    for (int i = 0; i < 4; i++)
#pragma unroll
        for (int j = 0; j < 4; j++) acc[i][j] = 0.f;

    for (int k0 = 0; k0 < K; k0 += 16) {
        {
            int r = tid >> 2, c4 = tid & 3;
            float4 v = *(const float4*)&A[(m0 + r) * K + k0 + c4 * 4];
            as[c4*4+0][r] = v.x; as[c4*4+1][r] = v.y;
            as[c4*4+2][r] = v.z; as[c4*4+3][r] = v.w;
        }
        {
            int r = tid >> 4, c4 = tid & 15;
            *(float4*)&bs[r][c4*4] = *(const float4*)&B[(k0 + r) * Nc + n0 + c4 * 4];
        }
        __syncthreads();
#pragma unroll
        for (int k = 0; k < 16; k++) {
            float4 av = *(const float4*)&as[k][ty * 4];
            float4 bv = *(const float4*)&bs[k][tx * 4];
            float a4[4] = {av.x, av.y, av.z, av.w};
            float b4[4] = {bv.x, bv.y, bv.z, bv.w};
#pragma unroll
            for (int i = 0; i < 4; i++)
#pragma unroll
                for (int j = 0; j < 4; j++) acc[i][j] += a4[i] * b4[j];
        }
        __syncthreads();
    }
#pragma unroll
    for (int i = 0; i < 4; i++) {
        int row = m0 + ty * 4 + i;
#pragma unroll
        for (int j = 0; j < 4; j++) {
            int col = n0 + tx * 4 + j;
            float v = acc[i][j];
            if (bias) v += bias[col];
            Co[row * Nc + col] = v;
        }
    }
}

// ---------------------------------------------------------------------------
// adj -> bitmask (with forced self-loop on the diagonal)
// ---------------------------------------------------------------------------
__global__ __launch_bounds__(256) void adjbits_kernel(const int* __restrict__ adj)
{
    int row  = blockIdx.x;
    int lane = threadIdx.x & 31;
    int w    = threadIdx.x >> 5;
#pragma unroll
    for (int wd = w; wd < NN/32; wd += 8) {
        int v = adj[(long)row * NN + wd * 32 + lane];
        unsigned bits = __ballot_sync(0xffffffffu, v != 0);
        if ((row >> 5) == wd) bits |= 1u << (row & 31);   // self loop
        if (lane == 0) g_adjbits[row * (NN/32) + wd] = bits;
    }
}

// ---------------------------------------------------------------------------
// Prep: per (head,node): s = h.att_dst, t = h.att_src -> r=e^{0.8s}, a=e^t, b=e^{0.2t}
// ---------------------------------------------------------------------------
__global__ __launch_bounds__(256) void prep_kernel(
    const float* __restrict__ att_src, const float* __restrict__ att_dst)
{
    int wid  = blockIdx.x * 8 + (threadIdx.x >> 5);
    int lane = threadIdx.x & 31;
    int hd = wid >> 12;
    int n  = wid & (NN - 1);
    const float* hp = g_h + n * EMB + hd * HC;
    float h0 = hp[lane], h1 = hp[lane + 32];
    float s = h0 * att_dst[hd*HC + lane] + h1 * att_dst[hd*HC + lane + 32];
    float t = h0 * att_src[hd*HC + lane] + h1 * att_src[hd*HC + lane + 32];
#pragma unroll
    for (int o = 16; o; o >>= 1) {
        s += __shfl_xor_sync(0xffffffffu, s, o);
        t += __shfl_xor_sync(0xffffffffu, t, o);
    }
    if (lane == 0) {
        g_r[wid] = expf(0.8f * s);
        g_a[wid] = expf(t);
        g_b[wid] = expf(0.2f * t);
    }
}

// ---------------------------------------------------------------------------
// Fused GAT aggregation, two independent 128-thread groups per block.
// Group g handles j-tiles (2t+g)*64. Per tile: bitmask phase-C (thread-per-row,
// denominator accumulated in-register) then 8x8 register-tile f32x2 GEMM.
// Final merge through smem + normalize + bias.
// ---------------------------------------------------------------------------
__global__ __launch_bounds__(256) void gat_kernel(const float* __restrict__ bias_att)
{
    extern __shared__ float sm[];
    // layout: ab_all[2*NN] | group0 {c[64][PADI], h[64][64]} | group1 {...}
    float* ab    = sm;                       // 8192 floats
    float* base0 = sm + 2 * NN;
    const int GSZ = TJ * PADI + TJ * HC;     // 12544 floats per group

    const int hd = blockIdx.y;
    const int i0 = blockIdx.x * TI;
    const int tid = threadIdx.x;
    const int g   = tid >> 7;                // group 0/1
    const int gt  = tid & 127;               // row-in-tile for phase C
    float* c_sm = base0 + g * GSZ;
    float* h_sm = c_sm + TJ * PADI;

    const float* ga = g_a + hd * NN;
    const float* gb = g_b + hd * NN;

    // preload a/b for the whole head (shared by both groups)
    for (int k = tid; k < NN; k += 256)
        ((float2*)ab)[k] = make_float2(ga[k], gb[k]);

    const float ri = g_r[hd * NN + i0 + gt];
    const unsigned* abits = g_adjbits + (long)(i0 + gt) * (NN/32);

    const int ty = gt >> 3, tx = gt & 7;
    ull acc[8][4];
#pragma unroll
    for (int i = 0; i < 8; i++)
#pragma unroll
        for (int j = 0; j < 4; j++) acc[i][j] = 0ull;
    float dreg = 0.f;

    __syncthreads();   // ab ready

    for (int t = 0; t < 32; t++) {
        const int j0 = (2 * t + g) * TJ;

        asm volatile("bar.sync %0, 128;" :: "r"(g + 1) : "memory");  // c/h free

        // load h tile: 64 rows x 64 floats = 1024 float4 slots, 128 threads
#pragma unroll
        for (int rr = 0; rr < 8; rr++) {
            int e = rr * 128 + gt;           // 0..1023
            int j = e >> 4, c4 = e & 15;
            *(float4*)&h_sm[j * HC + c4 * 4] =
                *(const float4*)&g_h[(j0 + j) * EMB + hd * HC + c4 * 4];
        }

        // phase C: this thread = local row gt, 64 source columns
        {
            unsigned w0 = abits[(j0 >> 5)];
            unsigned w1 = abits[(j0 >> 5) + 1];
            const float2* abj = (const float2*)ab + j0;
#pragma unroll
            for (int jj = 0; jj < 32; jj++) {
                float2 p0 = abj[jj];
                float v0 = fmaxf(ri * p0.x, p0.y);
                float cv0 = ((w0 >> jj) & 1u) ? v0 : 0.f;
                c_sm[jj * PADI + gt] = cv0;
                dreg += cv0;
                float2 p1 = abj[32 + jj];
                float v1 = fmaxf(ri * p1.x, p1.y);
                float cv1 = ((w1 >> jj) & 1u) ? v1 : 0.f;
                c_sm[(32 + jj) * PADI + gt] = cv1;
                dreg += cv1;
            }
        }

        asm volatile("bar.sync %0, 128;" :: "r"(g + 1) : "memory");  // c/h ready

        // GEMM: acc[i][c] += sum_j c[j][ty*8+i] * h[j][tx*8+c]
        const float* cb = c_sm + ty * 8;
        const float* hb = h_sm + tx * 8;
#pragma unroll 2
        for (int j = 0; j < TJ; j++) {
            float4 cA = *(const float4*)(cb + j * PADI);
            float4 cB = *(const float4*)(cb + j * PADI + 4);
            ulonglong2 hA = *(const ulonglong2*)(hb + j * HC);
            ulonglong2 hB = *(const ulonglong2*)(hb + j * HC + 4);
            ull cd[8] = { dup2(cA.x), dup2(cA.y), dup2(cA.z), dup2(cA.w),
                          dup2(cB.x), dup2(cB.y), dup2(cB.z), dup2(cB.w) };
#pragma unroll
            for (int ii = 0; ii < 8; ii++) {
                fma2(acc[ii][0], cd[ii], hA.x);
                fma2(acc[ii][1], cd[ii], hA.y);
                fma2(acc[ii][2], cd[ii], hB.x);
                fma2(acc[ii][3], cd[ii], hB.y);
            }
        }
    }

    __syncthreads();   // both groups done with their tiles

    // merge region reuses group1's smem
    const int MS = 70;                       // merge row stride (floats)
    float* mrg  = base0 + GSZ;               // 128*70 = 8960 floats
    float* d_sm = mrg + TI * MS;             // 2*128 floats

    d_sm[g * TI + gt] = dreg;
    if (g == 1) {
#pragma unroll
        for (int ii = 0; ii < 8; ii++) {
            int i = ty * 8 + ii;
#pragma unroll
            for (int cc = 0; cc < 4; cc++)
                *(ull*)&mrg[i * MS + tx * 8 + cc * 2] = acc[ii][cc];
        }
    }
    __syncthreads();

    if (g == 0) {
#pragma unroll
        for (int ii = 0; ii < 8; ii++) {
            int i = ty * 8 + ii;
            float inv = 1.0f / (d_sm[i] + d_sm[TI + i]);
            int row = i0 + i;
            float o[8];
#pragma unroll
            for (int cc = 0; cc < 4; cc++) {
                ull v = acc[ii][cc];
                ull m = *(const ull*)&mrg[i * MS + tx * 8 + cc * 2];
                float lo = __uint_as_float((unsigned)(v & 0xffffffffull))
                         + __uint_as_float((unsigned)(m & 0xffffffffull));
                float hi = __uint_as_float((unsigned)(v >> 32))
                         + __uint_as_float((unsigned)(m >> 32));
                int col = hd * HC + tx * 8 + cc * 2;
                o[cc*2]   = lo * inv + __ldg(bias_att + col);
                o[cc*2+1] = hi * inv + __ldg(bias_att + col + 1);
            }
            float* dst = g_att + (long)row * EMB + hd * HC + tx * 8;
            *(float4*)dst       = make_float4(o[0], o[1], o[2], o[3]);
            *(float4*)(dst + 4) = make_float4(o[4], o[5], o[6], o[7]);
        }
    }
}

// ---------------------------------------------------------------------------
// LayerNorm over last dim (256), one block per row.
// ---------------------------------------------------------------------------
__global__ __launch_bounds__(256) void ln_kernel(
    const float* __restrict__ gamma, const float* __restrict__ beta,
    float* __restrict__ out)
{
    __shared__ float red1[8], red2[8];
    int row = blockIdx.x;
    int tid = threadIdx.x;
    float v = g_y[row * EMB + tid];

    float s = v;
#pragma unroll
    for (int o = 16; o; o >>= 1) s += __shfl_xor_sync(0xffffffffu, s, o);
    if ((tid & 31) == 0) red1[tid >> 5] = s;
    __syncthreads();
    float mu = 0.f;
#pragma unroll
    for (int k = 0; k < 8; k++) mu += red1[k];
    mu *= (1.0f / EMB);

    float d = v - mu;
    float q = d * d;
#pragma unroll
    for (int o = 16; o; o >>= 1) q += __shfl_xor_sync(0xffffffffu, q, o);
    if ((tid & 31) == 0) red2[tid >> 5] = q;
    __syncthreads();
    float var = 0.f;
#pragma unroll
    for (int k = 0; k < 8; k++) var += red2[k];
    var *= (1.0f / EMB);

    out[row * EMB + tid] = d * rsqrtf(var + 1e-5f) * gamma[tid] + beta[tid];
}

// ---------------------------------------------------------------------------
extern "C" void kernel_launch(void* const* d_in, const int* in_sizes, int n_in,
                              void* d_out, int out_size)
{
    const float* x        = (const float*)d_in[0];
    const int*   adj      = (const int*)  d_in[1];
    const float* W_lin    = (const float*)d_in[2];
    const float* att_src  = (const float*)d_in[3];
    const float* att_dst  = (const float*)d_in[4];
    const float* bias_att = (const float*)d_in[5];
    const float* W_out    = (const float*)d_in[6];
    const float* b_out    = (const float*)d_in[7];
    const float* gamma    = (const float*)d_in[8];
    const float* beta     = (const float*)d_in[9];
    float* out = (float*)d_out;

    float *p_h, *p_att, *p_y;
    cudaGetSymbolAddress((void**)&p_h,   g_h);
    cudaGetSymbolAddress((void**)&p_att, g_att);
    cudaGetSymbolAddress((void**)&p_y,   g_y);

    const int gat_smem = (2*NN + 2*(TJ*PADI + TJ*HC)) * (int)sizeof(float); // 133120
    cudaFuncSetAttribute(gat_kernel, cudaFuncAttributeMaxDynamicSharedMemorySize, gat_smem);

    dim3 gemm_grid(EMB / 64, NN / 64);  // (4, 64)

    // 1) h = x @ W_lin
    gemm_bias_kernel<<<gemm_grid, 256>>>(x, W_lin, nullptr, p_h, NN, EMB, EMB);
    adjbits_kernel<<<NN, 256>>>(adj);
    prep_kernel<<<(NH * NN) / 8, 256>>>(att_src, att_dst);
    // 2) fused masked-softmax aggregation (+bias_att)
    dim3 gat_grid(NN / TI, NH);
    gat_kernel<<<gat_grid, 256, gat_smem>>>(bias_att);
    // 3) y = att @ W_out + b_out
    gemm_bias_kernel<<<gemm_grid, 256>>>(p_att, W_out, b_out, p_y, NN, EMB, EMB);
    // 4) LayerNorm -> out
    ln_kernel<<<NN, 256>>>(gamma, beta, out);
}